// round 4
// baseline (speedup 1.0000x reference)
#include <cuda_runtime.h>
#include <math.h>

#define FF    128
#define F3    384
#define NRBF  20
#define AMAX  50000
#define EMAX  500000
#define PI_F  3.14159265358979323846f
#define RCUT  5.0f

typedef unsigned long long u64;

// scratch (device globals: allocation-free)
__device__ float  g_sbuf[AMAX * F3];      // node MLP output [A,384]
__device__ int    g_cnt[AMAX];
__device__ int    g_cur[AMAX];
__device__ int    g_off[AMAX + 1];
__device__ float4 g_dir4[EMAX];           // xyz = direction, w = bitcast(idx_i)

// ---- packed fp32x2 helpers -------------------------------------------------
__device__ __forceinline__ u64 pk2(float lo, float hi) {
    u64 r; asm("mov.b64 %0, {%1, %2};" : "=l"(r) : "f"(lo), "f"(hi)); return r;
}
__device__ __forceinline__ u64 fma2(u64 a, u64 b, u64 c) {
    u64 d; asm("fma.rn.f32x2 %0, %1, %2, %3;" : "=l"(d) : "l"(a), "l"(b), "l"(c));
    return d;
}
__device__ __forceinline__ float2 upk2(u64 v) {
    float2 f; asm("mov.b64 {%0, %1}, %2;" : "=f"(f.x), "=f"(f.y) : "l"(v)); return f;
}

// ---------------------------------------------------------------------------
__global__ void hist_kernel(const int* __restrict__ idx_j, int E) {
    int e = blockIdx.x * blockDim.x + threadIdx.x;
    if (e < E) atomicAdd(&g_cnt[idx_j[e]], 1);
}

// single-block exclusive scan over g_cnt -> g_off / g_cur, 4 items/thread
__global__ __launch_bounds__(1024) void scan_kernel(int A) {
    __shared__ int wsum[32];
    __shared__ int s_carry;
    const int tid = threadIdx.x, lane = tid & 31, w = tid >> 5;
    if (tid == 0) s_carry = 0;
    __syncthreads();
    for (int base = 0; base < A; base += 4096) {
        int i0 = base + tid * 4;
        int v0 = (i0 + 0 < A) ? g_cnt[i0 + 0] : 0;
        int v1 = (i0 + 1 < A) ? g_cnt[i0 + 1] : 0;
        int v2 = (i0 + 2 < A) ? g_cnt[i0 + 2] : 0;
        int v3 = (i0 + 3 < A) ? g_cnt[i0 + 3] : 0;
        int t = v0 + v1 + v2 + v3;
        int incl = t;
#pragma unroll
        for (int d = 1; d < 32; d <<= 1) {
            int s = __shfl_up_sync(0xffffffffu, incl, d);
            if (lane >= d) incl += s;
        }
        if (lane == 31) wsum[w] = incl;
        __syncthreads();
        if (w == 0) {
            int s = wsum[lane];
#pragma unroll
            for (int d = 1; d < 32; d <<= 1) {
                int q = __shfl_up_sync(0xffffffffu, s, d);
                if (lane >= d) s += q;
            }
            wsum[lane] = s;
        }
        __syncthreads();
        int carry = s_carry;
        int excl = carry + incl - t + (w > 0 ? wsum[w - 1] : 0);
        if (i0 + 0 < A) { g_off[i0 + 0] = excl; g_cur[i0 + 0] = excl; } excl += v0;
        if (i0 + 1 < A) { g_off[i0 + 1] = excl; g_cur[i0 + 1] = excl; } excl += v1;
        if (i0 + 2 < A) { g_off[i0 + 2] = excl; g_cur[i0 + 2] = excl; } excl += v2;
        if (i0 + 3 < A) { g_off[i0 + 3] = excl; g_cur[i0 + 3] = excl; }
        __syncthreads();
        if (tid == 0) s_carry = carry + wsum[31];
        __syncthreads();
    }
    if (tid == 0) g_off[A] = s_carry;
}

__global__ void scatter_kernel(const int* __restrict__ idx_i,
                               const int* __restrict__ idx_j,
                               const float* __restrict__ directions, int E) {
    int e = blockIdx.x * blockDim.x + threadIdx.x;
    if (e >= E) return;
    int j = idx_j[e];
    int pos = atomicAdd(&g_cur[j], 1);
    float4 d;
    d.x = directions[(size_t)e * 3 + 0];
    d.y = directions[(size_t)e * 3 + 1];
    d.z = directions[(size_t)e * 3 + 2];
    d.w = __int_as_float(idx_i[e]);
    g_dir4[pos] = d;
}

// ---------------------------------------------------------------------------
// Node MLP: 16 rows per block (8 per thread-half), 256 threads, FFMA2.
__global__ __launch_bounds__(256, 2) void mlp_kernel(
    const float* __restrict__ scalars, const float* __restrict__ W1,
    const float* __restrict__ b1, const float* __restrict__ W2,
    const float* __restrict__ b2, int A)
{
    __shared__ float sx[16][FF];
    __shared__ float sh[16][FF];
    const int row0 = blockIdx.x * 16;
    const int tid  = threadIdx.x;

    for (int idx = tid; idx < 16 * 32; idx += 256) {
        int m = idx >> 5, c = idx & 31;
        float4 v = make_float4(0.f, 0.f, 0.f, 0.f);
        if (row0 + m < A)
            v = reinterpret_cast<const float4*>(scalars)[(size_t)(row0 + m) * 32 + c];
        *reinterpret_cast<float4*>(&sx[m][c * 4]) = v;
    }
    __syncthreads();

    const int n  = tid & 127;
    const int m0 = (tid >> 7) * 8;

    u64 acc[8];
#pragma unroll
    for (int i = 0; i < 8; i++) acc[i] = 0ull;

#pragma unroll 4
    for (int k = 0; k < FF; k += 4) {
        u64 wp0 = pk2(W1[(k + 0) * FF + n], W1[(k + 1) * FF + n]);
        u64 wp1 = pk2(W1[(k + 2) * FF + n], W1[(k + 3) * FF + n]);
#pragma unroll
        for (int i = 0; i < 8; i++) {
            ulonglong2 x2 = *reinterpret_cast<const ulonglong2*>(&sx[m0 + i][k]);
            acc[i] = fma2(x2.x, wp0, acc[i]);
            acc[i] = fma2(x2.y, wp1, acc[i]);
        }
    }
    {
        float bb = b1[n];
#pragma unroll
        for (int i = 0; i < 8; i++) {
            float2 p = upk2(acc[i]);
            float x = p.x + p.y + bb;
            sh[m0 + i][n] = x / (1.f + __expf(-x));
        }
    }
    __syncthreads();

    u64 a2[8][3];
#pragma unroll
    for (int i = 0; i < 8; i++)
#pragma unroll
        for (int c = 0; c < 3; c++) a2[i][c] = 0ull;

#pragma unroll 2
    for (int k = 0; k < FF; k += 4) {
        u64 wp[3][2];
#pragma unroll
        for (int c = 0; c < 3; c++) {
            wp[c][0] = pk2(W2[(k + 0) * F3 + n + c * 128], W2[(k + 1) * F3 + n + c * 128]);
            wp[c][1] = pk2(W2[(k + 2) * F3 + n + c * 128], W2[(k + 3) * F3 + n + c * 128]);
        }
#pragma unroll
        for (int i = 0; i < 8; i++) {
            ulonglong2 h2 = *reinterpret_cast<const ulonglong2*>(&sh[m0 + i][k]);
#pragma unroll
            for (int c = 0; c < 3; c++) {
                a2[i][c] = fma2(h2.x, wp[c][0], a2[i][c]);
                a2[i][c] = fma2(h2.y, wp[c][1], a2[i][c]);
            }
        }
    }
    {
        float c0 = b2[n], c1 = b2[n + 128], c2v = b2[n + 256];
#pragma unroll
        for (int i = 0; i < 8; i++) {
            int row = row0 + m0 + i;
            if (row < A) {
                float2 p0 = upk2(a2[i][0]);
                float2 p1 = upk2(a2[i][1]);
                float2 p2 = upk2(a2[i][2]);
                g_sbuf[(size_t)row * F3 + n]       = p0.x + p0.y + c0;
                g_sbuf[(size_t)row * F3 + n + 128] = p1.x + p1.y + c1;
                g_sbuf[(size_t)row * F3 + n + 256] = p2.x + p2.y + c2v;
            }
        }
    }
}

// ---------------------------------------------------------------------------
// Node-centric edge kernel: one warp per output node j (edges j-sorted, CSR).
// No atomics: each warp accumulates its node's delta_s / delta_v in registers
// and writes with plain STG.128. Covers ALL nodes, so no output memset needed.
__global__ __launch_bounds__(256, 2) void node_kernel(
    const float* __restrict__ vectors,
    const float* __restrict__ Wr, const float* __restrict__ br,
    float* __restrict__ out_v, float* __restrict__ out_s, int A)
{
    __shared__ float4 swr[NRBF * 96];   // Wr [20][384] as float4
    __shared__ float  sbr[F3];

    const int tid = threadIdx.x;
    for (int i2 = tid; i2 < NRBF * 96; i2 += 256)
        swr[i2] = reinterpret_cast<const float4*>(Wr)[i2];
    for (int i2 = tid; i2 < F3; i2 += 256) sbr[i2] = br[i2];
    __syncthreads();

    const int warp = tid >> 5;
    const int lane = tid & 31;
    const int j    = blockIdx.x * 8 + warp;
    if (j >= A) return;

    const int f4 = lane * 4;
    float4 brA = *reinterpret_cast<const float4*>(&sbr[f4]);
    float4 brB = *reinterpret_cast<const float4*>(&sbr[128 + f4]);
    float4 brC = *reinterpret_cast<const float4*>(&sbr[256 + f4]);

    float4 accS  = make_float4(0.f, 0.f, 0.f, 0.f);
    float4 accV0 = make_float4(0.f, 0.f, 0.f, 0.f);
    float4 accV1 = make_float4(0.f, 0.f, 0.f, 0.f);
    float4 accV2 = make_float4(0.f, 0.f, 0.f, 0.f);

    const int off = g_off[j];
    const int end = g_off[j + 1];

    for (int b = off; b < end; b += 4) {
        // ---- per-edge setup (uniform loads, every lane same address) ----
        float fcv[4], scv[4], inv[4], c2r[4], scur[4], sprev[4];
        int   ii[4];
        int   nv = end - b;            // valid edges this group (1..4)
#pragma unroll
        for (int e = 0; e < 4; e++) {
            float4 de = (e < nv) ? g_dir4[b + e] : make_float4(1.f, 0.f, 0.f, 0.f);
            ii[e] = (e < nv) ? __float_as_int(de.w) : 0;
            float nrm = sqrtf(de.x * de.x + de.y * de.y + de.z * de.z);
            inv[e] = 1.f / nrm;
            float x = (PI_F / RCUT) * nrm;
            float s1, c1;
            __sincosf(x, &s1, &c1);
            c2r[e]   = 2.f * c1;
            scur[e]  = s1;
            sprev[e] = 0.f;
            float delta = nrm - RCUT;
            float mask  = fminf(delta, 0.f) / delta;
            float fc    = 0.5f * (c1 + 1.f) * mask;
            fcv[e] = (e < nv) ? fc : 0.f;
            scv[e] = fcv[e] * inv[e];
        }

        // ---- rbf accumulation: sum_k sin(kx) * Wr[k] (FFMA2) ----
        ulonglong2 aA[4], aB[4], aC[4];
#pragma unroll
        for (int e = 0; e < 4; e++) {
            aA[e] = make_ulonglong2(0ull, 0ull);
            aB[e] = make_ulonglong2(0ull, 0ull);
            aC[e] = make_ulonglong2(0ull, 0ull);
        }
#pragma unroll
        for (int k = 0; k < NRBF; k++) {
            ulonglong2 wA = *reinterpret_cast<const ulonglong2*>(&swr[k * 96 + lane]);
            ulonglong2 wB = *reinterpret_cast<const ulonglong2*>(&swr[k * 96 + 32 + lane]);
            ulonglong2 wC = *reinterpret_cast<const ulonglong2*>(&swr[k * 96 + 64 + lane]);
#pragma unroll
            for (int e = 0; e < 4; e++) {
                float s = scur[e];
                u64 sd = pk2(s, s);
                aA[e].x = fma2(wA.x, sd, aA[e].x);
                aA[e].y = fma2(wA.y, sd, aA[e].y);
                aB[e].x = fma2(wB.x, sd, aB[e].x);
                aB[e].y = fma2(wB.y, sd, aB[e].y);
                aC[e].x = fma2(wC.x, sd, aC[e].x);
                aC[e].y = fma2(wC.y, sd, aC[e].y);
                float t = c2r[e] * s - sprev[e];
                sprev[e] = s;
                scur[e]  = t;
            }
        }

        // ---- per-edge epilogue: gather + combine into node accumulators ----
#pragma unroll
        for (int e = 0; e < 4; e++) {
            if (e >= nv) break;
            float f  = fcv[e];
            float sc = scv[e];

            float2 pAx = upk2(aA[e].x), pAy = upk2(aA[e].y);
            float2 pBx = upk2(aB[e].x), pBy = upk2(aB[e].y);
            float2 pCx = upk2(aC[e].x), pCy = upk2(aC[e].y);

            float4 rA, rB, rC;
            rA.x = sc * pAx.x + f * brA.x; rA.y = sc * pAx.y + f * brA.y;
            rA.z = sc * pAy.x + f * brA.z; rA.w = sc * pAy.y + f * brA.w;
            rB.x = sc * pBx.x + f * brB.x; rB.y = sc * pBx.y + f * brB.y;
            rB.z = sc * pBy.x + f * brB.z; rB.w = sc * pBy.y + f * brB.w;
            rC.x = sc * pCx.x + f * brC.x; rC.y = sc * pCx.y + f * brC.y;
            rC.z = sc * pCy.x + f * brC.z; rC.w = sc * pCy.y + f * brC.w;

            size_t ib = (size_t)ii[e] * F3 + f4;
            float4 sA = *reinterpret_cast<const float4*>(&g_sbuf[ib]);
            float4 sB = *reinterpret_cast<const float4*>(&g_sbuf[ib + 128]);
            float4 sC = *reinterpret_cast<const float4*>(&g_sbuf[ib + 256]);

            accS.x += sA.x * rA.x; accS.y += sA.y * rA.y;
            accS.z += sA.z * rA.z; accS.w += sA.w * rA.w;

            float4 dv1, dv2;
            dv1.x = sB.x * rB.x; dv1.y = sB.y * rB.y; dv1.z = sB.z * rB.z; dv1.w = sB.w * rB.w;
            dv2.x = sC.x * rC.x; dv2.y = sC.y * rC.y; dv2.z = sC.z * rC.z; dv2.w = sC.w * rC.w;

            // reload direction (L1 hit) to recover dh without keeping regs
            float4 de = g_dir4[b + e];
            float dh0 = de.x * inv[e], dh1 = de.y * inv[e], dh2 = de.z * inv[e];

            size_t vb = (size_t)ii[e] * F3 + f4;
            float4 v0 = *reinterpret_cast<const float4*>(&vectors[vb]);
            float4 v1 = *reinterpret_cast<const float4*>(&vectors[vb + 128]);
            float4 v2 = *reinterpret_cast<const float4*>(&vectors[vb + 256]);

            accV0.x += v0.x * dv1.x + dv2.x * dh0; accV0.y += v0.y * dv1.y + dv2.y * dh0;
            accV0.z += v0.z * dv1.z + dv2.z * dh0; accV0.w += v0.w * dv1.w + dv2.w * dh0;
            accV1.x += v1.x * dv1.x + dv2.x * dh1; accV1.y += v1.y * dv1.y + dv2.y * dh1;
            accV1.z += v1.z * dv1.z + dv2.z * dh1; accV1.w += v1.w * dv1.w + dv2.w * dh1;
            accV2.x += v2.x * dv1.x + dv2.x * dh2; accV2.y += v2.y * dv1.y + dv2.y * dh2;
            accV2.z += v2.z * dv1.z + dv2.z * dh2; accV2.w += v2.w * dv1.w + dv2.w * dh2;
        }
    }

    // plain stores — this warp exclusively owns node j
    *reinterpret_cast<float4*>(&out_s[(size_t)j * FF + f4])        = accS;
    *reinterpret_cast<float4*>(&out_v[(size_t)j * F3 + f4])        = accV0;
    *reinterpret_cast<float4*>(&out_v[(size_t)j * F3 + 128 + f4])  = accV1;
    *reinterpret_cast<float4*>(&out_v[(size_t)j * F3 + 256 + f4])  = accV2;
}

// ---------------------------------------------------------------------------
extern "C" void kernel_launch(void* const* d_in, const int* in_sizes, int n_in,
                              void* d_out, int out_size) {
    const float* vectors    = (const float*)d_in[0];
    const float* scalars    = (const float*)d_in[1];
    const float* directions = (const float*)d_in[2];
    const int*   idx_i      = (const int*)d_in[3];
    const int*   idx_j      = (const int*)d_in[4];
    const float* W1         = (const float*)d_in[5];
    const float* b1         = (const float*)d_in[6];
    const float* W2         = (const float*)d_in[7];
    const float* b2         = (const float*)d_in[8];
    const float* Wr         = (const float*)d_in[9];
    const float* br         = (const float*)d_in[10];

    const int A = in_sizes[0] / (3 * FF);
    const int E = in_sizes[2] / 3;

    float* out   = (float*)d_out;
    float* out_v = out;                          // delta_v: A x 3 x F
    float* out_s = out + (size_t)A * 3 * FF;     // delta_s: A x 1 x F

    static void* p_cnt = nullptr;
    if (!p_cnt) cudaGetSymbolAddress(&p_cnt, g_cnt);

    cudaMemsetAsync(p_cnt, 0, (size_t)A * sizeof(int), 0);
    hist_kernel<<<(E + 255) / 256, 256>>>(idx_j, E);
    scan_kernel<<<1, 1024>>>(A);
    scatter_kernel<<<(E + 255) / 256, 256>>>(idx_i, idx_j, directions, E);

    mlp_kernel<<<(A + 15) / 16, 256>>>(scalars, W1, b1, W2, b2, A);
    node_kernel<<<(A + 7) / 8, 256>>>(vectors, Wr, br, out_v, out_s, A);
}

// round 5
// speedup vs baseline: 3.3420x; 3.3420x over previous
#include <cuda_runtime.h>
#include <math.h>

#define FF    128
#define F3    384
#define NRBF  20
#define AMAX  50000
#define EMAX  500000
#define PI_F  3.14159265358979323846f
#define RCUT  5.0f

typedef unsigned long long u64;

// scratch (device globals: allocation-free)
__device__ float  g_sbuf[AMAX * F3];      // node MLP output [A,384]
__device__ int    g_cnt[AMAX];
__device__ int    g_cur[AMAX];
__device__ int    g_off[AMAX + 1];
__device__ float4 g_dir4[EMAX];           // xyz = direction, w = bitcast(idx_i)
__device__ u64    g_W1p[64 * FF];         // W1 packed k-pairs: [k2][n]
__device__ u64    g_W2p[64 * F3];         // W2 packed k-pairs: [k2][c*128+n]

// ---- packed fp32x2 helpers -------------------------------------------------
__device__ __forceinline__ u64 pk2(float lo, float hi) {
    u64 r; asm("mov.b64 %0, {%1, %2};" : "=l"(r) : "f"(lo), "f"(hi)); return r;
}
__device__ __forceinline__ u64 fma2(u64 a, u64 b, u64 c) {
    u64 d; asm("fma.rn.f32x2 %0, %1, %2, %3;" : "=l"(d) : "l"(a), "l"(b), "l"(c));
    return d;
}
__device__ __forceinline__ float2 upk2(u64 v) {
    float2 f; asm("mov.b64 {%0, %1}, %2;" : "=f"(f.x), "=f"(f.y) : "l"(v)); return f;
}

// ---------------------------------------------------------------------------
__global__ void pack_kernel(const float* __restrict__ W1,
                            const float* __restrict__ W2) {
    int t = blockIdx.x * blockDim.x + threadIdx.x;   // 0 .. 64*480-1
    if (t < 64 * FF) {
        int k2 = t >> 7, n = t & 127;
        g_W1p[t] = pk2(W1[(2 * k2) * FF + n], W1[(2 * k2 + 1) * FF + n]);
    }
    int t2 = t - 64 * FF;
    if (t2 >= 0 && t2 < 64 * F3) {
        int k2 = t2 / F3, cn = t2 % F3;
        g_W2p[t2] = pk2(W2[(2 * k2) * F3 + cn], W2[(2 * k2 + 1) * F3 + cn]);
    }
}

__global__ void hist_kernel(const int* __restrict__ idx_j, int E) {
    int e = blockIdx.x * blockDim.x + threadIdx.x;
    if (e < E) atomicAdd(&g_cnt[idx_j[e]], 1);
}

// single-block exclusive scan over g_cnt -> g_off / g_cur, 4 items/thread
__global__ __launch_bounds__(1024) void scan_kernel(int A) {
    __shared__ int wsum[32];
    __shared__ int s_carry;
    const int tid = threadIdx.x, lane = tid & 31, w = tid >> 5;
    if (tid == 0) s_carry = 0;
    __syncthreads();
    for (int base = 0; base < A; base += 4096) {
        int i0 = base + tid * 4;
        int v0 = (i0 + 0 < A) ? g_cnt[i0 + 0] : 0;
        int v1 = (i0 + 1 < A) ? g_cnt[i0 + 1] : 0;
        int v2 = (i0 + 2 < A) ? g_cnt[i0 + 2] : 0;
        int v3 = (i0 + 3 < A) ? g_cnt[i0 + 3] : 0;
        int t = v0 + v1 + v2 + v3;
        int incl = t;
#pragma unroll
        for (int d = 1; d < 32; d <<= 1) {
            int s = __shfl_up_sync(0xffffffffu, incl, d);
            if (lane >= d) incl += s;
        }
        if (lane == 31) wsum[w] = incl;
        __syncthreads();
        if (w == 0) {
            int s = wsum[lane];
#pragma unroll
            for (int d = 1; d < 32; d <<= 1) {
                int q = __shfl_up_sync(0xffffffffu, s, d);
                if (lane >= d) s += q;
            }
            wsum[lane] = s;
        }
        __syncthreads();
        int carry = s_carry;
        int excl = carry + incl - t + (w > 0 ? wsum[w - 1] : 0);
        if (i0 + 0 < A) { g_off[i0 + 0] = excl; g_cur[i0 + 0] = excl; } excl += v0;
        if (i0 + 1 < A) { g_off[i0 + 1] = excl; g_cur[i0 + 1] = excl; } excl += v1;
        if (i0 + 2 < A) { g_off[i0 + 2] = excl; g_cur[i0 + 2] = excl; } excl += v2;
        if (i0 + 3 < A) { g_off[i0 + 3] = excl; g_cur[i0 + 3] = excl; }
        __syncthreads();
        if (tid == 0) s_carry = carry + wsum[31];
        __syncthreads();
    }
    if (tid == 0) g_off[A] = s_carry;
}

__global__ void scatter_kernel(const int* __restrict__ idx_i,
                               const int* __restrict__ idx_j,
                               const float* __restrict__ directions, int E) {
    int e = blockIdx.x * blockDim.x + threadIdx.x;
    if (e >= E) return;
    int j = idx_j[e];
    int pos = atomicAdd(&g_cur[j], 1);
    float4 d;
    d.x = directions[(size_t)e * 3 + 0];
    d.y = directions[(size_t)e * 3 + 1];
    d.z = directions[(size_t)e * 3 + 2];
    d.w = __int_as_float(idx_i[e]);
    g_dir4[pos] = d;
}

// ---------------------------------------------------------------------------
// Node MLP: 16 rows per block (8 per thread-half), 256 threads, FFMA2,
// pre-packed f32x2 weights (halved LDG issue).
__global__ __launch_bounds__(256, 2) void mlp_kernel(
    const float* __restrict__ scalars,
    const float* __restrict__ b1, const float* __restrict__ b2, int A)
{
    __shared__ float sx[16][FF];
    __shared__ float sh[16][FF];
    const int row0 = blockIdx.x * 16;
    const int tid  = threadIdx.x;

    for (int idx = tid; idx < 16 * 32; idx += 256) {
        int m = idx >> 5, c = idx & 31;
        float4 v = make_float4(0.f, 0.f, 0.f, 0.f);
        if (row0 + m < A)
            v = reinterpret_cast<const float4*>(scalars)[(size_t)(row0 + m) * 32 + c];
        *reinterpret_cast<float4*>(&sx[m][c * 4]) = v;
    }
    __syncthreads();

    const int n  = tid & 127;
    const int m0 = (tid >> 7) * 8;

    u64 acc[8];
#pragma unroll
    for (int i = 0; i < 8; i++) acc[i] = 0ull;

#pragma unroll 4
    for (int k2 = 0; k2 < 64; k2 += 2) {         // k-chunk of 4
        u64 wp0 = g_W1p[k2 * FF + n];
        u64 wp1 = g_W1p[(k2 + 1) * FF + n];
#pragma unroll
        for (int i = 0; i < 8; i++) {
            ulonglong2 x2 = *reinterpret_cast<const ulonglong2*>(&sx[m0 + i][k2 * 2]);
            acc[i] = fma2(x2.x, wp0, acc[i]);
            acc[i] = fma2(x2.y, wp1, acc[i]);
        }
    }
    {
        float bb = b1[n];
#pragma unroll
        for (int i = 0; i < 8; i++) {
            float2 p = upk2(acc[i]);
            float x = p.x + p.y + bb;
            sh[m0 + i][n] = x / (1.f + __expf(-x));
        }
    }
    __syncthreads();

    u64 a2[8][3];
#pragma unroll
    for (int i = 0; i < 8; i++)
#pragma unroll
        for (int c = 0; c < 3; c++) a2[i][c] = 0ull;

#pragma unroll 2
    for (int k2 = 0; k2 < 64; k2 += 2) {
        u64 wp[3][2];
#pragma unroll
        for (int c = 0; c < 3; c++) {
            wp[c][0] = g_W2p[k2 * F3 + c * 128 + n];
            wp[c][1] = g_W2p[(k2 + 1) * F3 + c * 128 + n];
        }
#pragma unroll
        for (int i = 0; i < 8; i++) {
            ulonglong2 h2 = *reinterpret_cast<const ulonglong2*>(&sh[m0 + i][k2 * 2]);
#pragma unroll
            for (int c = 0; c < 3; c++) {
                a2[i][c] = fma2(h2.x, wp[c][0], a2[i][c]);
                a2[i][c] = fma2(h2.y, wp[c][1], a2[i][c]);
            }
        }
    }
    {
        float c0 = b2[n], c1 = b2[n + 128], c2v = b2[n + 256];
#pragma unroll
        for (int i = 0; i < 8; i++) {
            int row = row0 + m0 + i;
            if (row < A) {
                float2 p0 = upk2(a2[i][0]);
                float2 p1 = upk2(a2[i][1]);
                float2 p2 = upk2(a2[i][2]);
                g_sbuf[(size_t)row * F3 + n]       = p0.x + p0.y + c0;
                g_sbuf[(size_t)row * F3 + n + 128] = p1.x + p1.y + c1;
                g_sbuf[(size_t)row * F3 + n + 256] = p2.x + p2.y + c2v;
            }
        }
    }
}

// ---------------------------------------------------------------------------
// Node-centric edge kernel: one warp per output node j (edges j-sorted, CSR).
// Register-disciplined: only Chebyshev state + accumulators live across the
// k-loop; fc/scale/idx_i recomputed in the epilogue from a uniform reload.
__global__ __launch_bounds__(256, 2) void node_kernel(
    const float* __restrict__ vectors,
    const float* __restrict__ Wr, const float* __restrict__ br,
    float* __restrict__ out_v, float* __restrict__ out_s, int A)
{
    __shared__ float4 swr[NRBF * 96];   // Wr [20][384] as float4
    __shared__ float  sbr[F3];

    const int tid = threadIdx.x;
    for (int i2 = tid; i2 < NRBF * 96; i2 += 256)
        swr[i2] = reinterpret_cast<const float4*>(Wr)[i2];
    for (int i2 = tid; i2 < F3; i2 += 256) sbr[i2] = br[i2];
    __syncthreads();

    const int warp = tid >> 5;
    const int lane = tid & 31;
    const int j    = blockIdx.x * 8 + warp;
    if (j >= A) return;

    const int f4 = lane * 4;

    float4 accS  = make_float4(0.f, 0.f, 0.f, 0.f);
    float4 accV0 = make_float4(0.f, 0.f, 0.f, 0.f);
    float4 accV1 = make_float4(0.f, 0.f, 0.f, 0.f);
    float4 accV2 = make_float4(0.f, 0.f, 0.f, 0.f);

    const int off = g_off[j];
    const int end = g_off[j + 1];

    for (int b = off; b < end; b += 4) {
        const int nv = end - b;            // valid edges this group (>=1)

        // ---- setup: Chebyshev state only (12 regs) ----
        float c2r[4], scur[4], sprev[4];
#pragma unroll
        for (int e = 0; e < 4; e++) {
            float4 de = (e < nv) ? g_dir4[b + e] : make_float4(1.f, 0.f, 0.f, 0.f);
            float nrm = sqrtf(de.x * de.x + de.y * de.y + de.z * de.z);
            float s1, c1;
            __sincosf((PI_F / RCUT) * nrm, &s1, &c1);
            c2r[e]   = 2.f * c1;
            scur[e]  = (e < nv) ? s1 : 0.f;
            sprev[e] = 0.f;
        }

        // ---- rbf accumulation: sum_k sin(kx) * Wr[k] (FFMA2) ----
        ulonglong2 aA[4], aB[4], aC[4];
#pragma unroll
        for (int e = 0; e < 4; e++) {
            aA[e] = make_ulonglong2(0ull, 0ull);
            aB[e] = make_ulonglong2(0ull, 0ull);
            aC[e] = make_ulonglong2(0ull, 0ull);
        }
#pragma unroll
        for (int k = 0; k < NRBF; k++) {
            ulonglong2 wA = *reinterpret_cast<const ulonglong2*>(&swr[k * 96 + lane]);
            ulonglong2 wB = *reinterpret_cast<const ulonglong2*>(&swr[k * 96 + 32 + lane]);
            ulonglong2 wC = *reinterpret_cast<const ulonglong2*>(&swr[k * 96 + 64 + lane]);
#pragma unroll
            for (int e = 0; e < 4; e++) {
                float s = scur[e];
                u64 sd = pk2(s, s);
                aA[e].x = fma2(wA.x, sd, aA[e].x);
                aA[e].y = fma2(wA.y, sd, aA[e].y);
                aB[e].x = fma2(wB.x, sd, aB[e].x);
                aB[e].y = fma2(wB.y, sd, aB[e].y);
                aC[e].x = fma2(wC.x, sd, aC[e].x);
                aC[e].y = fma2(wC.y, sd, aC[e].y);
                float t = c2r[e] * s - sprev[e];
                sprev[e] = s;
                scur[e]  = t;
            }
        }

        // ---- epilogue: recompute per-edge scalars, gather, accumulate ----
#pragma unroll 1
        for (int e = 0; e < 4; e++) {
            if (e >= nv) break;
            float4 de = g_dir4[b + e];                 // uniform L1 hit
            int ii = __float_as_int(de.w);
            float nrm = sqrtf(de.x * de.x + de.y * de.y + de.z * de.z);
            float inv = 1.f / nrm;
            float c1  = __cosf((PI_F / RCUT) * nrm);
            float delta = nrm - RCUT;
            float mask  = fminf(delta, 0.f) / delta;
            float f  = 0.5f * (c1 + 1.f) * mask;
            float sc = f * inv;

            float2 pAx = upk2(aA[e].x), pAy = upk2(aA[e].y);
            float2 pBx = upk2(aB[e].x), pBy = upk2(aB[e].y);
            float2 pCx = upk2(aC[e].x), pCy = upk2(aC[e].y);

            float4 brA = *reinterpret_cast<const float4*>(&sbr[f4]);
            float4 brB = *reinterpret_cast<const float4*>(&sbr[128 + f4]);
            float4 brC = *reinterpret_cast<const float4*>(&sbr[256 + f4]);

            float4 rA, rB, rC;
            rA.x = sc * pAx.x + f * brA.x; rA.y = sc * pAx.y + f * brA.y;
            rA.z = sc * pAy.x + f * brA.z; rA.w = sc * pAy.y + f * brA.w;
            rB.x = sc * pBx.x + f * brB.x; rB.y = sc * pBx.y + f * brB.y;
            rB.z = sc * pBy.x + f * brB.z; rB.w = sc * pBy.y + f * brB.w;
            rC.x = sc * pCx.x + f * brC.x; rC.y = sc * pCx.y + f * brC.y;
            rC.z = sc * pCy.x + f * brC.z; rC.w = sc * pCy.y + f * brC.w;

            size_t ib = (size_t)ii * F3 + f4;
            float4 sA = *reinterpret_cast<const float4*>(&g_sbuf[ib]);
            float4 sB = *reinterpret_cast<const float4*>(&g_sbuf[ib + 128]);
            float4 sC = *reinterpret_cast<const float4*>(&g_sbuf[ib + 256]);

            accS.x += sA.x * rA.x; accS.y += sA.y * rA.y;
            accS.z += sA.z * rA.z; accS.w += sA.w * rA.w;

            float4 dv1, dv2;
            dv1.x = sB.x * rB.x; dv1.y = sB.y * rB.y; dv1.z = sB.z * rB.z; dv1.w = sB.w * rB.w;
            dv2.x = sC.x * rC.x; dv2.y = sC.y * rC.y; dv2.z = sC.z * rC.z; dv2.w = sC.w * rC.w;

            float dh0 = de.x * inv, dh1 = de.y * inv, dh2 = de.z * inv;

            size_t vb = (size_t)ii * F3 + f4;
            float4 v0 = *reinterpret_cast<const float4*>(&vectors[vb]);
            float4 v1 = *reinterpret_cast<const float4*>(&vectors[vb + 128]);
            float4 v2 = *reinterpret_cast<const float4*>(&vectors[vb + 256]);

            accV0.x += v0.x * dv1.x + dv2.x * dh0; accV0.y += v0.y * dv1.y + dv2.y * dh0;
            accV0.z += v0.z * dv1.z + dv2.z * dh0; accV0.w += v0.w * dv1.w + dv2.w * dh0;
            accV1.x += v1.x * dv1.x + dv2.x * dh1; accV1.y += v1.y * dv1.y + dv2.y * dh1;
            accV1.z += v1.z * dv1.z + dv2.z * dh1; accV1.w += v1.w * dv1.w + dv2.w * dh1;
            accV2.x += v2.x * dv1.x + dv2.x * dh2; accV2.y += v2.y * dv1.y + dv2.y * dh2;
            accV2.z += v2.z * dv1.z + dv2.z * dh2; accV2.w += v2.w * dv1.w + dv2.w * dh2;
        }
    }

    // plain stores — this warp exclusively owns node j
    *reinterpret_cast<float4*>(&out_s[(size_t)j * FF + f4])        = accS;
    *reinterpret_cast<float4*>(&out_v[(size_t)j * F3 + f4])        = accV0;
    *reinterpret_cast<float4*>(&out_v[(size_t)j * F3 + 128 + f4])  = accV1;
    *reinterpret_cast<float4*>(&out_v[(size_t)j * F3 + 256 + f4])  = accV2;
}

// ---------------------------------------------------------------------------
extern "C" void kernel_launch(void* const* d_in, const int* in_sizes, int n_in,
                              void* d_out, int out_size) {
    const float* vectors    = (const float*)d_in[0];
    const float* scalars    = (const float*)d_in[1];
    const float* directions = (const float*)d_in[2];
    const int*   idx_i      = (const int*)d_in[3];
    const int*   idx_j      = (const int*)d_in[4];
    const float* W1         = (const float*)d_in[5];
    const float* b1         = (const float*)d_in[6];
    const float* W2         = (const float*)d_in[7];
    const float* b2         = (const float*)d_in[8];
    const float* Wr         = (const float*)d_in[9];
    const float* br         = (const float*)d_in[10];

    const int A = in_sizes[0] / (3 * FF);
    const int E = in_sizes[2] / 3;

    float* out   = (float*)d_out;
    float* out_v = out;                          // delta_v: A x 3 x F
    float* out_s = out + (size_t)A * 3 * FF;     // delta_s: A x 1 x F

    static void* p_cnt = nullptr;
    static cudaStream_t s2 = nullptr;
    static cudaEvent_t ev0 = nullptr, ev1 = nullptr;
    if (!p_cnt) {
        cudaGetSymbolAddress(&p_cnt, g_cnt);
        cudaStreamCreateWithFlags(&s2, cudaStreamNonBlocking);
        cudaEventCreateWithFlags(&ev0, cudaEventDisableTiming);
        cudaEventCreateWithFlags(&ev1, cudaEventDisableTiming);
    }

    // fork: sort chain on s2, MLP chain on the main stream
    cudaEventRecord(ev0, 0);
    cudaStreamWaitEvent(s2, ev0, 0);

    cudaMemsetAsync(p_cnt, 0, (size_t)A * sizeof(int), s2);
    hist_kernel<<<(E + 255) / 256, 256, 0, s2>>>(idx_j, E);
    scan_kernel<<<1, 1024, 0, s2>>>(A);
    scatter_kernel<<<(E + 255) / 256, 256, 0, s2>>>(idx_i, idx_j, directions, E);
    cudaEventRecord(ev1, s2);

    pack_kernel<<<(64 * (FF + F3) + 255) / 256, 256>>>(W1, W2);
    mlp_kernel<<<(A + 15) / 16, 256>>>(scalars, b1, b2, A);

    // join, then node-centric combine
    cudaStreamWaitEvent(0, ev1, 0);
    node_kernel<<<(A + 7) / 8, 256>>>(vectors, Wr, br, out_v, out_s, A);
}

// round 6
// speedup vs baseline: 3.4114x; 1.0208x over previous
#include <cuda_runtime.h>
#include <cuda_fp16.h>
#include <math.h>

#define FF    128
#define F3    384
#define NRBF  20
#define AMAX  50000
#define EMAX  500000
#define PI_F  3.14159265358979323846f
#define RCUT  5.0f

typedef unsigned long long u64;

// scratch (device globals: allocation-free)
__device__ __half     g_sbuf[AMAX * F3];      // node MLP output [A,384] fp16
__device__ __half     g_vech[AMAX * F3];      // fp16 copy of vectors [A,3,F]
__device__ int        g_cnt[AMAX];
__device__ int        g_cur[AMAX];
__device__ int        g_off[AMAX + 1];
__device__ float4     g_dir4[EMAX];           // xyz = direction, w = bitcast(idx_i)
__device__ ulonglong2 g_W1q[32 * FF];         // W1 4k-chunks packed f32x2
__device__ ulonglong2 g_W2q[32 * F3];         // W2 4k-chunks packed f32x2

// ---- packed fp32x2 helpers -------------------------------------------------
__device__ __forceinline__ u64 pk2(float lo, float hi) {
    u64 r; asm("mov.b64 %0, {%1, %2};" : "=l"(r) : "f"(lo), "f"(hi)); return r;
}
__device__ __forceinline__ u64 fma2(u64 a, u64 b, u64 c) {
    u64 d; asm("fma.rn.f32x2 %0, %1, %2, %3;" : "=l"(d) : "l"(a), "l"(b), "l"(c));
    return d;
}
__device__ __forceinline__ float2 upk2(u64 v) {
    float2 f; asm("mov.b64 {%0, %1}, %2;" : "=f"(f.x), "=f"(f.y) : "l"(v)); return f;
}
// load 4 halves -> float4
__device__ __forceinline__ float4 ldh4(const __half* p) {
    uint2 u = *reinterpret_cast<const uint2*>(p);
    float2 a = __half22float2(*reinterpret_cast<__half2*>(&u.x));
    float2 b = __half22float2(*reinterpret_cast<__half2*>(&u.y));
    return make_float4(a.x, a.y, b.x, b.y);
}

// ---------------------------------------------------------------------------
__global__ void pack_kernel(const float* __restrict__ W1,
                            const float* __restrict__ W2) {
    int t = blockIdx.x * blockDim.x + threadIdx.x;   // 0 .. 32*512-1
    if (t < 32 * FF) {
        int k4 = t >> 7, n = t & 127;
        ulonglong2 v;
        v.x = pk2(W1[(4 * k4 + 0) * FF + n], W1[(4 * k4 + 1) * FF + n]);
        v.y = pk2(W1[(4 * k4 + 2) * FF + n], W1[(4 * k4 + 3) * FF + n]);
        g_W1q[t] = v;
    }
    int t2 = t - 32 * FF;
    if (t2 >= 0 && t2 < 32 * F3) {
        int k4 = t2 / F3, cn = t2 % F3;
        ulonglong2 v;
        v.x = pk2(W2[(4 * k4 + 0) * F3 + cn], W2[(4 * k4 + 1) * F3 + cn]);
        v.y = pk2(W2[(4 * k4 + 2) * F3 + cn], W2[(4 * k4 + 3) * F3 + cn]);
        g_W2q[t2] = v;
    }
}

__global__ void vconv_kernel(const float* __restrict__ vectors, int n4) {
    int t = blockIdx.x * blockDim.x + threadIdx.x;
    if (t >= n4) return;
    float4 v = reinterpret_cast<const float4*>(vectors)[t];
    __half2 h0 = __floats2half2_rn(v.x, v.y);
    __half2 h1 = __floats2half2_rn(v.z, v.w);
    uint2 u;
    u.x = *reinterpret_cast<unsigned*>(&h0);
    u.y = *reinterpret_cast<unsigned*>(&h1);
    *reinterpret_cast<uint2*>(&g_vech[(size_t)t * 4]) = u;
}

__global__ void hist_kernel(const int* __restrict__ idx_j, int E) {
    int e = blockIdx.x * blockDim.x + threadIdx.x;
    if (e < E) atomicAdd(&g_cnt[idx_j[e]], 1);
}

// single-block exclusive scan over g_cnt -> g_off / g_cur, 4 items/thread
__global__ __launch_bounds__(1024) void scan_kernel(int A) {
    __shared__ int wsum[32];
    __shared__ int s_carry;
    const int tid = threadIdx.x, lane = tid & 31, w = tid >> 5;
    if (tid == 0) s_carry = 0;
    __syncthreads();
    for (int base = 0; base < A; base += 4096) {
        int i0 = base + tid * 4;
        int v0 = (i0 + 0 < A) ? g_cnt[i0 + 0] : 0;
        int v1 = (i0 + 1 < A) ? g_cnt[i0 + 1] : 0;
        int v2 = (i0 + 2 < A) ? g_cnt[i0 + 2] : 0;
        int v3 = (i0 + 3 < A) ? g_cnt[i0 + 3] : 0;
        int t = v0 + v1 + v2 + v3;
        int incl = t;
#pragma unroll
        for (int d = 1; d < 32; d <<= 1) {
            int s = __shfl_up_sync(0xffffffffu, incl, d);
            if (lane >= d) incl += s;
        }
        if (lane == 31) wsum[w] = incl;
        __syncthreads();
        if (w == 0) {
            int s = wsum[lane];
#pragma unroll
            for (int d = 1; d < 32; d <<= 1) {
                int q = __shfl_up_sync(0xffffffffu, s, d);
                if (lane >= d) s += q;
            }
            wsum[lane] = s;
        }
        __syncthreads();
        int carry = s_carry;
        int excl = carry + incl - t + (w > 0 ? wsum[w - 1] : 0);
        if (i0 + 0 < A) { g_off[i0 + 0] = excl; g_cur[i0 + 0] = excl; } excl += v0;
        if (i0 + 1 < A) { g_off[i0 + 1] = excl; g_cur[i0 + 1] = excl; } excl += v1;
        if (i0 + 2 < A) { g_off[i0 + 2] = excl; g_cur[i0 + 2] = excl; } excl += v2;
        if (i0 + 3 < A) { g_off[i0 + 3] = excl; g_cur[i0 + 3] = excl; }
        __syncthreads();
        if (tid == 0) s_carry = carry + wsum[31];
        __syncthreads();
    }
    if (tid == 0) g_off[A] = s_carry;
}

__global__ void scatter_kernel(const int* __restrict__ idx_i,
                               const int* __restrict__ idx_j,
                               const float* __restrict__ directions, int E) {
    int e = blockIdx.x * blockDim.x + threadIdx.x;
    if (e >= E) return;
    int j = idx_j[e];
    int pos = atomicAdd(&g_cur[j], 1);
    float4 d;
    d.x = directions[(size_t)e * 3 + 0];
    d.y = directions[(size_t)e * 3 + 1];
    d.z = directions[(size_t)e * 3 + 2];
    d.w = __int_as_float(idx_i[e]);
    g_dir4[pos] = d;
}

// ---------------------------------------------------------------------------
// Node MLP: 16 rows per block (8 per thread-half), 256 threads, FFMA2,
// pre-packed f32x2 weights as LDG.128, fp16 output.
__global__ __launch_bounds__(256, 2) void mlp_kernel(
    const float* __restrict__ scalars,
    const float* __restrict__ b1, const float* __restrict__ b2, int A)
{
    __shared__ float sx[16][FF];
    __shared__ float sh[16][FF];
    const int row0 = blockIdx.x * 16;
    const int tid  = threadIdx.x;

    for (int idx = tid; idx < 16 * 32; idx += 256) {
        int m = idx >> 5, c = idx & 31;
        float4 v = make_float4(0.f, 0.f, 0.f, 0.f);
        if (row0 + m < A)
            v = reinterpret_cast<const float4*>(scalars)[(size_t)(row0 + m) * 32 + c];
        *reinterpret_cast<float4*>(&sx[m][c * 4]) = v;
    }
    __syncthreads();

    const int n  = tid & 127;
    const int m0 = (tid >> 7) * 8;

    u64 acc[8];
#pragma unroll
    for (int i = 0; i < 8; i++) acc[i] = 0ull;

#pragma unroll 4
    for (int k4 = 0; k4 < 32; k4++) {            // chunk of 4 k's
        ulonglong2 w = g_W1q[k4 * FF + n];
#pragma unroll
        for (int i = 0; i < 8; i++) {
            ulonglong2 x2 = *reinterpret_cast<const ulonglong2*>(&sx[m0 + i][k4 * 4]);
            acc[i] = fma2(x2.x, w.x, acc[i]);
            acc[i] = fma2(x2.y, w.y, acc[i]);
        }
    }
    {
        float bb = b1[n];
#pragma unroll
        for (int i = 0; i < 8; i++) {
            float2 p = upk2(acc[i]);
            float x = p.x + p.y + bb;
            sh[m0 + i][n] = x / (1.f + __expf(-x));
        }
    }
    __syncthreads();

    u64 a2[8][3];
#pragma unroll
    for (int i = 0; i < 8; i++)
#pragma unroll
        for (int c = 0; c < 3; c++) a2[i][c] = 0ull;

#pragma unroll 2
    for (int k4 = 0; k4 < 32; k4++) {
        ulonglong2 w0 = g_W2q[k4 * F3 + n];
        ulonglong2 w1 = g_W2q[k4 * F3 + 128 + n];
        ulonglong2 w2 = g_W2q[k4 * F3 + 256 + n];
#pragma unroll
        for (int i = 0; i < 8; i++) {
            ulonglong2 h2 = *reinterpret_cast<const ulonglong2*>(&sh[m0 + i][k4 * 4]);
            a2[i][0] = fma2(h2.x, w0.x, a2[i][0]);
            a2[i][0] = fma2(h2.y, w0.y, a2[i][0]);
            a2[i][1] = fma2(h2.x, w1.x, a2[i][1]);
            a2[i][1] = fma2(h2.y, w1.y, a2[i][1]);
            a2[i][2] = fma2(h2.x, w2.x, a2[i][2]);
            a2[i][2] = fma2(h2.y, w2.y, a2[i][2]);
        }
    }
    {
        float c0 = b2[n], c1 = b2[n + 128], c2v = b2[n + 256];
#pragma unroll
        for (int i = 0; i < 8; i++) {
            int row = row0 + m0 + i;
            if (row < A) {
                float2 p0 = upk2(a2[i][0]);
                float2 p1 = upk2(a2[i][1]);
                float2 p2 = upk2(a2[i][2]);
                g_sbuf[(size_t)row * F3 + n]       = __float2half(p0.x + p0.y + c0);
                g_sbuf[(size_t)row * F3 + n + 128] = __float2half(p1.x + p1.y + c1);
                g_sbuf[(size_t)row * F3 + n + 256] = __float2half(p2.x + p2.y + c2v);
            }
        }
    }
}

// ---------------------------------------------------------------------------
// Node-centric edge kernel: one warp per output node j (edges j-sorted, CSR).
// fp16 gather arrays keep the whole random-access working set L2-resident.
__global__ __launch_bounds__(256, 2) void node_kernel(
    const float* __restrict__ Wr, const float* __restrict__ br,
    float* __restrict__ out_v, float* __restrict__ out_s, int A)
{
    __shared__ float4 swr[NRBF * 96];   // Wr [20][384] as float4
    __shared__ float  sbr[F3];

    const int tid = threadIdx.x;
    for (int i2 = tid; i2 < NRBF * 96; i2 += 256)
        swr[i2] = reinterpret_cast<const float4*>(Wr)[i2];
    for (int i2 = tid; i2 < F3; i2 += 256) sbr[i2] = br[i2];
    __syncthreads();

    const int warp = tid >> 5;
    const int lane = tid & 31;
    const int j    = blockIdx.x * 8 + warp;
    if (j >= A) return;

    const int f4 = lane * 4;

    float4 accS  = make_float4(0.f, 0.f, 0.f, 0.f);
    float4 accV0 = make_float4(0.f, 0.f, 0.f, 0.f);
    float4 accV1 = make_float4(0.f, 0.f, 0.f, 0.f);
    float4 accV2 = make_float4(0.f, 0.f, 0.f, 0.f);

    const int off = g_off[j];
    const int end = g_off[j + 1];

    for (int b = off; b < end; b += 4) {
        const int nv = end - b;            // valid edges this group (>=1)

        // ---- setup: Chebyshev state only ----
        float c2r[4], scur[4], sprev[4];
#pragma unroll
        for (int e = 0; e < 4; e++) {
            float4 de = (e < nv) ? g_dir4[b + e] : make_float4(1.f, 0.f, 0.f, 0.f);
            float nrm = sqrtf(de.x * de.x + de.y * de.y + de.z * de.z);
            float s1, c1;
            __sincosf((PI_F / RCUT) * nrm, &s1, &c1);
            c2r[e]   = 2.f * c1;
            scur[e]  = (e < nv) ? s1 : 0.f;
            sprev[e] = 0.f;
        }

        // ---- rbf accumulation: sum_k sin(kx) * Wr[k] (FFMA2) ----
        ulonglong2 aA[4], aB[4], aC[4];
#pragma unroll
        for (int e = 0; e < 4; e++) {
            aA[e] = make_ulonglong2(0ull, 0ull);
            aB[e] = make_ulonglong2(0ull, 0ull);
            aC[e] = make_ulonglong2(0ull, 0ull);
        }
#pragma unroll
        for (int k = 0; k < NRBF; k++) {
            ulonglong2 wA = *reinterpret_cast<const ulonglong2*>(&swr[k * 96 + lane]);
            ulonglong2 wB = *reinterpret_cast<const ulonglong2*>(&swr[k * 96 + 32 + lane]);
            ulonglong2 wC = *reinterpret_cast<const ulonglong2*>(&swr[k * 96 + 64 + lane]);
#pragma unroll
            for (int e = 0; e < 4; e++) {
                float s = scur[e];
                u64 sd = pk2(s, s);
                aA[e].x = fma2(wA.x, sd, aA[e].x);
                aA[e].y = fma2(wA.y, sd, aA[e].y);
                aB[e].x = fma2(wB.x, sd, aB[e].x);
                aB[e].y = fma2(wB.y, sd, aB[e].y);
                aC[e].x = fma2(wC.x, sd, aC[e].x);
                aC[e].y = fma2(wC.y, sd, aC[e].y);
                float t = c2r[e] * s - sprev[e];
                sprev[e] = s;
                scur[e]  = t;
            }
        }

        // ---- epilogue: recompute per-edge scalars, gather (fp16, L2-hit) ----
#pragma unroll 1
        for (int e = 0; e < 4; e++) {
            if (e >= nv) break;
            float4 de = g_dir4[b + e];                 // uniform L1 hit
            int ii = __float_as_int(de.w);
            float nrm = sqrtf(de.x * de.x + de.y * de.y + de.z * de.z);
            float inv = 1.f / nrm;
            float c1  = __cosf((PI_F / RCUT) * nrm);
            float delta = nrm - RCUT;
            float mask  = fminf(delta, 0.f) / delta;
            float f  = 0.5f * (c1 + 1.f) * mask;
            float sc = f * inv;

            float2 pAx = upk2(aA[e].x), pAy = upk2(aA[e].y);
            float2 pBx = upk2(aB[e].x), pBy = upk2(aB[e].y);
            float2 pCx = upk2(aC[e].x), pCy = upk2(aC[e].y);

            float4 brA = *reinterpret_cast<const float4*>(&sbr[f4]);
            float4 brB = *reinterpret_cast<const float4*>(&sbr[128 + f4]);
            float4 brC = *reinterpret_cast<const float4*>(&sbr[256 + f4]);

            float4 rA, rB, rC;
            rA.x = sc * pAx.x + f * brA.x; rA.y = sc * pAx.y + f * brA.y;
            rA.z = sc * pAy.x + f * brA.z; rA.w = sc * pAy.y + f * brA.w;
            rB.x = sc * pBx.x + f * brB.x; rB.y = sc * pBx.y + f * brB.y;
            rB.z = sc * pBy.x + f * brB.z; rB.w = sc * pBy.y + f * brB.w;
            rC.x = sc * pCx.x + f * brC.x; rC.y = sc * pCx.y + f * brC.y;
            rC.z = sc * pCy.x + f * brC.z; rC.w = sc * pCy.y + f * brC.w;

            size_t ib = (size_t)ii * F3 + f4;
            float4 sA = ldh4(&g_sbuf[ib]);
            float4 sB = ldh4(&g_sbuf[ib + 128]);
            float4 sC = ldh4(&g_sbuf[ib + 256]);

            accS.x += sA.x * rA.x; accS.y += sA.y * rA.y;
            accS.z += sA.z * rA.z; accS.w += sA.w * rA.w;

            float4 dv1, dv2;
            dv1.x = sB.x * rB.x; dv1.y = sB.y * rB.y; dv1.z = sB.z * rB.z; dv1.w = sB.w * rB.w;
            dv2.x = sC.x * rC.x; dv2.y = sC.y * rC.y; dv2.z = sC.z * rC.z; dv2.w = sC.w * rC.w;

            float dh0 = de.x * inv, dh1 = de.y * inv, dh2 = de.z * inv;

            float4 v0 = ldh4(&g_vech[ib]);
            float4 v1 = ldh4(&g_vech[ib + 128]);
            float4 v2 = ldh4(&g_vech[ib + 256]);

            accV0.x += v0.x * dv1.x + dv2.x * dh0; accV0.y += v0.y * dv1.y + dv2.y * dh0;
            accV0.z += v0.z * dv1.z + dv2.z * dh0; accV0.w += v0.w * dv1.w + dv2.w * dh0;
            accV1.x += v1.x * dv1.x + dv2.x * dh1; accV1.y += v1.y * dv1.y + dv2.y * dh1;
            accV1.z += v1.z * dv1.z + dv2.z * dh1; accV1.w += v1.w * dv1.w + dv2.w * dh1;
            accV2.x += v2.x * dv1.x + dv2.x * dh2; accV2.y += v2.y * dv1.y + dv2.y * dh2;
            accV2.z += v2.z * dv1.z + dv2.z * dh2; accV2.w += v2.w * dv1.w + dv2.w * dh2;
        }
    }

    // streaming stores (evict-first) — keep gather arrays L2-resident
    __stcs(reinterpret_cast<float4*>(&out_s[(size_t)j * FF + f4]),       accS);
    __stcs(reinterpret_cast<float4*>(&out_v[(size_t)j * F3 + f4]),       accV0);
    __stcs(reinterpret_cast<float4*>(&out_v[(size_t)j * F3 + 128 + f4]), accV1);
    __stcs(reinterpret_cast<float4*>(&out_v[(size_t)j * F3 + 256 + f4]), accV2);
}

// ---------------------------------------------------------------------------
extern "C" void kernel_launch(void* const* d_in, const int* in_sizes, int n_in,
                              void* d_out, int out_size) {
    const float* vectors    = (const float*)d_in[0];
    const float* scalars    = (const float*)d_in[1];
    const float* directions = (const float*)d_in[2];
    const int*   idx_i      = (const int*)d_in[3];
    const int*   idx_j      = (const int*)d_in[4];
    const float* W1         = (const float*)d_in[5];
    const float* b1         = (const float*)d_in[6];
    const float* W2         = (const float*)d_in[7];
    const float* b2         = (const float*)d_in[8];
    const float* Wr         = (const float*)d_in[9];
    const float* br         = (const float*)d_in[10];

    const int A = in_sizes[0] / (3 * FF);
    const int E = in_sizes[2] / 3;

    float* out   = (float*)d_out;
    float* out_v = out;                          // delta_v: A x 3 x F
    float* out_s = out + (size_t)A * 3 * FF;     // delta_s: A x 1 x F

    static void* p_cnt = nullptr;
    static cudaStream_t s2 = nullptr;
    static cudaEvent_t ev0 = nullptr, ev1 = nullptr;
    if (!p_cnt) {
        cudaGetSymbolAddress(&p_cnt, g_cnt);
        cudaStreamCreateWithFlags(&s2, cudaStreamNonBlocking);
        cudaEventCreateWithFlags(&ev0, cudaEventDisableTiming);
        cudaEventCreateWithFlags(&ev1, cudaEventDisableTiming);
    }

    // fork: sort chain + vector fp16 convert on s2, pack+MLP on main stream
    cudaEventRecord(ev0, 0);
    cudaStreamWaitEvent(s2, ev0, 0);

    cudaMemsetAsync(p_cnt, 0, (size_t)A * sizeof(int), s2);
    hist_kernel<<<(E + 255) / 256, 256, 0, s2>>>(idx_j, E);
    scan_kernel<<<1, 1024, 0, s2>>>(A);
    scatter_kernel<<<(E + 255) / 256, 256, 0, s2>>>(idx_i, idx_j, directions, E);
    {
        int n4 = (A * F3) / 4;
        vconv_kernel<<<(n4 + 255) / 256, 256, 0, s2>>>(vectors, n4);
    }
    cudaEventRecord(ev1, s2);

    pack_kernel<<<(32 * (FF + F3) + 255) / 256, 256>>>(W1, W2);
    mlp_kernel<<<(A + 15) / 16, 256>>>(scalars, b1, b2, A);

    // join, then node-centric combine
    cudaStreamWaitEvent(0, ev1, 0);
    node_kernel<<<(A + 7) / 8, 256>>>(Wr, br, out_v, out_s, A);
}